// round 12
// baseline (speedup 1.0000x reference)
#include <cuda_runtime.h>
#include <cuda_fp16.h>
#include <math.h>
#include <stdint.h>

// Problem constants
#define BATCH_M   16384   // B*S
#define DIM_D     768
#define DIM_N     2304    // 3*D
#define NUM_T     10
#define RANK_R    16
#define SEG       (RANK_R * DIM_D)

// GEMM tiling (R5 config — proven fastest): CTA 128x128, 8 warps, BK=32
#define BM 128
#define BN 128
#define BK 32
#define KSTAGES (DIM_D / BK)       // 24

#define ROWB     80
#define ARRB     10240             // 128 rows * 80B
#define STAGEB   20480
#define NSTAGE   4
#define SMEM_TOTAL (NSTAGE * STAGEB)

// sumsq: 4 partial blocks per (tensor,task) segment
#define NSUMSQ_BLOCKS 160

// fused prep: convert (16 floats/thread) + weff
#define NCONV_BLOCKS 3072          // 3072 blocks * 256 thr * 16 elems = X
#define WEFF_DTILES  3             // 768 / 256
#define WEFF_EROWS   8
#define WEFF_ETILES  (DIM_N / WEFF_EROWS)   // 288

// Device scratch (no cudaMalloc allowed)
__device__ float g_part[NSUMSQ_BLOCKS];     // 4 partials per segment
__device__ __align__(16) unsigned short g_Xh[(size_t)BATCH_M * DIM_D];
__device__ __align__(16) unsigned short g_Wh[(size_t)DIM_N * DIM_D];

// ---------------------------------------------------------------------------
// Helpers
// ---------------------------------------------------------------------------
__device__ __forceinline__ uint32_t smem_u32(const void* p) {
    uint32_t a;
    asm("{ .reg .u64 t; cvta.to.shared.u64 t, %1; cvt.u32.u64 %0, t; }" : "=r"(a) : "l"(p));
    return a;
}
#define CP16(dst, src) \
    asm volatile("cp.async.cg.shared.global [%0], [%1], 16;" :: "r"(dst), "l"(src))
#define CP_COMMIT() asm volatile("cp.async.commit_group;" ::: "memory")
#define CP_WAIT2()  asm volatile("cp.async.wait_group 2;"  ::: "memory")

__device__ __forceinline__ void ldsm_x4(uint32_t* r, uint32_t addr) {
    asm volatile("ldmatrix.sync.aligned.m8n8.x4.shared.b16 {%0,%1,%2,%3}, [%4];"
        : "=r"(r[0]), "=r"(r[1]), "=r"(r[2]), "=r"(r[3]) : "r"(addr));
}
__device__ __forceinline__ void mma_fp16(float* c, const uint32_t* a,
                                         uint32_t b0, uint32_t b1) {
    asm volatile("mma.sync.aligned.m16n8k16.row.col.f32.f16.f16.f32 "
        "{%0,%1,%2,%3},{%4,%5,%6,%7},{%8,%9},{%0,%1,%2,%3};"
        : "+f"(c[0]), "+f"(c[1]), "+f"(c[2]), "+f"(c[3])
        : "r"(a[0]), "r"(a[1]), "r"(a[2]), "r"(a[3]), "r"(b0), "r"(b1));
}

// ---------------------------------------------------------------------------
// Kernel 1: partial Frobenius sums. 160 blocks = 4 per (tensor,task) segment.
// Each block reduces SEG/4 = 3072 floats; weff sums the 4 partials inline.
// ---------------------------------------------------------------------------
__global__ __launch_bounds__(256)
void k_sumsq(const float* __restrict__ Aq, const float* __restrict__ Bq,
             const float* __restrict__ Av, const float* __restrict__ Bv) {
    const int b = blockIdx.x;           // 0..159
    const int seg = b >> 2;             // 0..39
    const int quarter = b & 3;
    const float* base;
    switch (seg / NUM_T) {
        case 0:  base = Aq; break;
        case 1:  base = Bq; break;
        case 2:  base = Av; break;
        default: base = Bv; break;
    }
    const float4* p = (const float4*)(base + (seg % NUM_T) * SEG) + quarter * (SEG / 16);
    float s = 0.f;
    #pragma unroll
    for (int i = 0; i < 3; i++) {       // 3 float4 per thread, front-batched
        float4 v = __ldg(p + threadIdx.x + i * 256);
        s += v.x * v.x + v.y * v.y + v.z * v.z + v.w * v.w;
    }
    #pragma unroll
    for (int o = 16; o > 0; o >>= 1)
        s += __shfl_xor_sync(0xFFFFFFFF, s, o);
    __shared__ float red[8];
    if ((threadIdx.x & 31) == 0) red[threadIdx.x >> 5] = s;
    __syncthreads();
    if (threadIdx.x == 0) {
        float t = 0.f;
        #pragma unroll
        for (int i = 0; i < 8; i++) t += red[i];
        g_part[b] = t;
    }
}

// ---------------------------------------------------------------------------
// Kernel 2: fused prep — grid-partitioned (R8-proven fusion).
//   blocks [0, NCONV_BLOCKS):    quantize X -> fp16 (16 elems/thread, HBM)
//   blocks [NCONV_BLOCKS, +864): build W_eff -> fp16 (L2-latency bound),
//                                softmax weights + sumsq reduce inline.
// ---------------------------------------------------------------------------
__global__ __launch_bounds__(256)
void k_prep1(const float* __restrict__ x,
             const float* __restrict__ Aq, const float* __restrict__ Bq,
             const float* __restrict__ Av, const float* __restrict__ Bv,
             const float* __restrict__ qkvw,
             const float* __restrict__ logits, const float* __restrict__ alpha) {
    if (blockIdx.x < NCONV_BLOCKS) {
        size_t i = ((size_t)blockIdx.x * 256 + threadIdx.x) * 16;
        float4 v0 = __ldg((const float4*)(x + i));
        float4 v1 = __ldg((const float4*)(x + i + 4));
        float4 v2 = __ldg((const float4*)(x + i + 8));
        float4 v3 = __ldg((const float4*)(x + i + 12));
        uint4 h0, h1;
        h0.x = (uint32_t)__half_as_ushort(__float2half(v0.x))
             | ((uint32_t)__half_as_ushort(__float2half(v0.y)) << 16);
        h0.y = (uint32_t)__half_as_ushort(__float2half(v0.z))
             | ((uint32_t)__half_as_ushort(__float2half(v0.w)) << 16);
        h0.z = (uint32_t)__half_as_ushort(__float2half(v1.x))
             | ((uint32_t)__half_as_ushort(__float2half(v1.y)) << 16);
        h0.w = (uint32_t)__half_as_ushort(__float2half(v1.z))
             | ((uint32_t)__half_as_ushort(__float2half(v1.w)) << 16);
        h1.x = (uint32_t)__half_as_ushort(__float2half(v2.x))
             | ((uint32_t)__half_as_ushort(__float2half(v2.y)) << 16);
        h1.y = (uint32_t)__half_as_ushort(__float2half(v2.z))
             | ((uint32_t)__half_as_ushort(__float2half(v2.w)) << 16);
        h1.z = (uint32_t)__half_as_ushort(__float2half(v3.x))
             | ((uint32_t)__half_as_ushort(__float2half(v3.y)) << 16);
        h1.w = (uint32_t)__half_as_ushort(__float2half(v3.z))
             | ((uint32_t)__half_as_ushort(__float2half(v3.w)) << 16);
        *(uint4*)(g_Xh + i)     = h0;
        *(uint4*)(g_Xh + i + 8) = h1;
        return;
    }

    // ---- W_eff: 8 e-rows x 256 d-cols per block ----
    const int bid = blockIdx.x - NCONV_BLOCKS;
    const int d   = (bid % WEFF_DTILES) * 256 + threadIdx.x;
    const int e0  = (bid / WEFF_DTILES) * WEFF_EROWS;
    const int tx  = threadIdx.x;

    float acc[WEFF_EROWS];
    #pragma unroll
    for (int e = 0; e < WEFF_EROWS; e++) acc[e] = 0.f;

    bool is_q = (e0 < DIM_D);
    bool is_v = (e0 >= 2 * DIM_D);
    if (is_q || is_v) {
        __shared__ float sw[NUM_T];
        __shared__ __align__(16) float sB[NUM_T * RANK_R * WEFF_EROWS];  // [i][e]

        if (tx == 0) {
            float mx = -1e30f;
            float lg[NUM_T];
            #pragma unroll
            for (int t = 0; t < NUM_T; t++) { lg[t] = __ldg(logits + t); mx = fmaxf(mx, lg[t]); }
            float e[NUM_T], se = 0.f;
            #pragma unroll
            for (int t = 0; t < NUM_T; t++) { e[t] = expf(lg[t] - mx); se += e[t]; }
            #pragma unroll
            for (int t = 0; t < NUM_T; t++) {
                float coef = (e[t] / se) * __ldg(alpha + t);
                int sa = is_q ? t : (20 + t);        // A-matrix segment
                int sb2 = is_q ? (10 + t) : (30 + t); // B-matrix segment
                float ssa = g_part[4 * sa]  + g_part[4 * sa + 1]
                          + g_part[4 * sa + 2] + g_part[4 * sa + 3];
                float ssb = g_part[4 * sb2] + g_part[4 * sb2 + 1]
                          + g_part[4 * sb2 + 2] + g_part[4 * sb2 + 3];
                sw[t] = coef / (sqrtf(ssa) * sqrtf(ssb) + 1e-8f);
            }
        }
        __syncthreads();

        const float* Am = is_q ? Aq : Av;
        const float* Bm = is_q ? Bq : Bv;
        int el0 = is_q ? e0 : (e0 - 2 * DIM_D);
        for (int idx = tx; idx < NUM_T * RANK_R * WEFF_EROWS; idx += 256) {
            int i = idx >> 3, e = idx & 7;
            int t = i >> 4,  r = i & 15;
            sB[idx] = sw[t] * Bm[((size_t)t * DIM_D + el0 + e) * RANK_R + r];
        }
        __syncthreads();

        const float4* sB4 = (const float4*)sB;
        #pragma unroll 32
        for (int i = 0; i < NUM_T * RANK_R; i++) {
            float a = __ldg(Am + (size_t)i * DIM_D + d);
            float4 b0 = sB4[i * 2 + 0];
            float4 b1 = sB4[i * 2 + 1];
            acc[0] += a * b0.x;  acc[1] += a * b0.y;
            acc[2] += a * b0.z;  acc[3] += a * b0.w;
            acc[4] += a * b1.x;  acc[5] += a * b1.y;
            acc[6] += a * b1.z;  acc[7] += a * b1.w;
        }
    }
    #pragma unroll
    for (int e = 0; e < WEFF_EROWS; e++) {
        float val = qkvw[(size_t)(e0 + e) * DIM_D + d] + acc[e];
        g_Wh[(size_t)(e0 + e) * DIM_D + d] = __half_as_ushort(__float2half(val));
    }
}

// ---------------------------------------------------------------------------
// Kernel 3: HMMA GEMM  out = Xh @ Wh^T + bias   (R5 config, verbatim)
// ---------------------------------------------------------------------------
__global__ __launch_bounds__(256, 2)
void k_gemm_mma(const float* __restrict__ bias, float* __restrict__ out) {
    extern __shared__ __align__(128) char smem[];
    const uint32_t sb = smem_u32(smem);
    const int tid = threadIdx.x;
    const int lid = tid & 31;
    const int wid = tid >> 5;
    const int wm = wid & 3;          // 4 warps in M, 32 rows each
    const int wn = wid >> 2;         // 2 warps in N, 64 cols each
    const int m0 = blockIdx.y * BM;
    const int n0 = blockIdx.x * BN;

    float acc[2][8][4];
    #pragma unroll
    for (int i = 0; i < 2; i++)
        #pragma unroll
        for (int j = 0; j < 8; j++)
            #pragma unroll
            for (int q = 0; q < 4; q++) acc[i][j][q] = 0.f;

    const uint32_t a_off = (uint32_t)(lid & 15) * ROWB + (uint32_t)(lid >> 4) * 16;
    const int b_nloc = (lid < 16) ? (lid & 7) : 8 + (lid & 7);
    const uint32_t b_off = (uint32_t)b_nloc * ROWB + (uint32_t)((lid >> 3) & 1) * 16;

    auto load_stage = [&](int s) {
        uint32_t buf = sb + (uint32_t)(s % NSTAGE) * STAGEB;
        int k0 = s * BK;
        #pragma unroll
        for (int i = 0; i < 4; i++) {
            int v = tid + i * 256;
            int arr = v >> 9;            // 0: Xh, 1: Wh
            int idx = v & 511;
            int r = idx >> 2, c = idx & 3;
            uint32_t dst = buf + (uint32_t)arr * ARRB + (uint32_t)r * ROWB + (uint32_t)c * 16;
            const unsigned short* src = arr == 0
                ? g_Xh + (size_t)(m0 + r) * DIM_D + k0 + c * 8
                : g_Wh + (size_t)(n0 + r) * DIM_D + k0 + c * 8;
            CP16(dst, src);
        }
    };

    load_stage(0); CP_COMMIT();
    load_stage(1); CP_COMMIT();
    load_stage(2); CP_COMMIT();

    for (int s = 0; s < KSTAGES; s++) {
        CP_WAIT2();
        __syncthreads();
        if (s + 3 < KSTAGES) load_stage(s + 3);
        CP_COMMIT();

        uint32_t buf = sb + (uint32_t)(s % NSTAGE) * STAGEB;
        #pragma unroll
        for (int kk = 0; kk < 2; kk++) {
            uint32_t koff = (uint32_t)kk * 32;
            uint32_t ra[2][4];
            #pragma unroll
            for (int mt = 0; mt < 2; mt++)
                ldsm_x4(ra[mt], buf + (uint32_t)(wm * 32 + mt * 16) * ROWB + koff + a_off);
            #pragma unroll
            for (int half = 0; half < 2; half++) {
                uint32_t rb[2][4];
                #pragma unroll
                for (int g = 0; g < 2; g++)
                    ldsm_x4(rb[g], buf + ARRB +
                        (uint32_t)(wn * 64 + (half * 2 + g) * 16) * ROWB + koff + b_off);
                #pragma unroll
                for (int mt = 0; mt < 2; mt++)
                    #pragma unroll
                    for (int n4 = 0; n4 < 4; n4++) {
                        uint32_t b0 = rb[n4 >> 1][(n4 & 1) * 2];
                        uint32_t b1 = rb[n4 >> 1][(n4 & 1) * 2 + 1];
                        mma_fp16(acc[mt][half * 4 + n4], ra[mt], b0, b1);
                    }
            }
        }
    }

    const int r0 = m0 + wm * 32 + (lid >> 2);
    const int cb = n0 + wn * 64 + (lid & 3) * 2;
    #pragma unroll
    for (int nt = 0; nt < 8; nt++) {
        float2 bv = *(const float2*)(bias + cb + nt * 8);
        #pragma unroll
        for (int mt = 0; mt < 2; mt++) {
            int r = r0 + mt * 16;
            float2 v0 = make_float2(acc[mt][nt][0] + bv.x, acc[mt][nt][1] + bv.y);
            float2 v1 = make_float2(acc[mt][nt][2] + bv.x, acc[mt][nt][3] + bv.y);
            *(float2*)(out + (size_t)r * DIM_N + cb + nt * 8) = v0;
            *(float2*)(out + (size_t)(r + 8) * DIM_N + cb + nt * 8) = v1;
        }
    }
}

// ---------------------------------------------------------------------------
// Launch
// ---------------------------------------------------------------------------
extern "C" void kernel_launch(void* const* d_in, const int* in_sizes, int n_in,
                              void* d_out, int out_size) {
    const float* x      = (const float*)d_in[0];
    const float* Aq     = (const float*)d_in[1];
    const float* Bq     = (const float*)d_in[2];
    const float* Av     = (const float*)d_in[3];
    const float* Bv     = (const float*)d_in[4];
    const float* qkvw   = (const float*)d_in[5];
    const float* qkvb   = (const float*)d_in[6];
    const float* logits = (const float*)d_in[7];
    const float* alpha  = (const float*)d_in[8];
    float* out = (float*)d_out;

    cudaFuncSetAttribute(k_gemm_mma, cudaFuncAttributeMaxDynamicSharedMemorySize, SMEM_TOTAL);

    k_sumsq   <<<NSUMSQ_BLOCKS, 256>>>(Aq, Bq, Av, Bv);
    k_prep1   <<<NCONV_BLOCKS + WEFF_DTILES * WEFF_ETILES, 256>>>(
                  x, Aq, Bq, Av, Bv, qkvw, logits, alpha);
    k_gemm_mma<<<dim3(DIM_N / BN, BATCH_M / BM), 256, SMEM_TOTAL>>>(qkvb, out);
}

// round 13
// speedup vs baseline: 1.0573x; 1.0573x over previous
#include <cuda_runtime.h>
#include <cuda_fp16.h>
#include <math.h>
#include <stdint.h>

// Problem constants
#define BATCH_M   16384   // B*S
#define DIM_D     768
#define DIM_N     2304    // 3*D
#define NUM_T     10
#define RANK_R    16
#define SEG       (RANK_R * DIM_D)

// GEMM tiling (R5 config — proven fastest): CTA 128x128, 8 warps, BK=32
#define BM 128
#define BN 128
#define BK 32
#define KSTAGES (DIM_D / BK)       // 24

#define ROWB     80
#define ARRB     10240             // 128 rows * 80B
#define STAGEB   20480
#define NSTAGE   4
#define SMEM_TOTAL (NSTAGE * STAGEB)

// sumsq: 4 partial blocks per (tensor,task) segment
#define NSUMSQ_BLOCKS 160

// fused prep: weff FIRST (overlaps convert), then convert (16 floats/thread)
#define WEFF_DTILES  3             // 768 / 256
#define WEFF_EROWS   8
#define WEFF_ETILES  (DIM_N / WEFF_EROWS)            // 288
#define NWEFF_BLOCKS (WEFF_DTILES * WEFF_ETILES)     // 864
#define NCONV_BLOCKS 3072          // 3072 blocks * 256 thr * 16 elems = X

// Device scratch (no cudaMalloc allowed)
__device__ float g_part[NSUMSQ_BLOCKS];     // 4 partials per segment
__device__ __align__(16) unsigned short g_Xh[(size_t)BATCH_M * DIM_D];
__device__ __align__(16) unsigned short g_Wh[(size_t)DIM_N * DIM_D];

// ---------------------------------------------------------------------------
// Helpers
// ---------------------------------------------------------------------------
__device__ __forceinline__ uint32_t smem_u32(const void* p) {
    uint32_t a;
    asm("{ .reg .u64 t; cvta.to.shared.u64 t, %1; cvt.u32.u64 %0, t; }" : "=r"(a) : "l"(p));
    return a;
}
#define CP16(dst, src) \
    asm volatile("cp.async.cg.shared.global [%0], [%1], 16;" :: "r"(dst), "l"(src))
#define CP_COMMIT() asm volatile("cp.async.commit_group;" ::: "memory")
#define CP_WAIT2()  asm volatile("cp.async.wait_group 2;"  ::: "memory")

__device__ __forceinline__ void ldsm_x4(uint32_t* r, uint32_t addr) {
    asm volatile("ldmatrix.sync.aligned.m8n8.x4.shared.b16 {%0,%1,%2,%3}, [%4];"
        : "=r"(r[0]), "=r"(r[1]), "=r"(r[2]), "=r"(r[3]) : "r"(addr));
}
__device__ __forceinline__ void mma_fp16(float* c, const uint32_t* a,
                                         uint32_t b0, uint32_t b1) {
    asm volatile("mma.sync.aligned.m16n8k16.row.col.f32.f16.f16.f32 "
        "{%0,%1,%2,%3},{%4,%5,%6,%7},{%8,%9},{%0,%1,%2,%3};"
        : "+f"(c[0]), "+f"(c[1]), "+f"(c[2]), "+f"(c[3])
        : "r"(a[0]), "r"(a[1]), "r"(a[2]), "r"(a[3]), "r"(b0), "r"(b1));
}

// ---------------------------------------------------------------------------
// Kernel 1: partial Frobenius sums. 160 blocks = 4 per (tensor,task) segment.
// ---------------------------------------------------------------------------
__global__ __launch_bounds__(256)
void k_sumsq(const float* __restrict__ Aq, const float* __restrict__ Bq,
             const float* __restrict__ Av, const float* __restrict__ Bv) {
    const int b = blockIdx.x;           // 0..159
    const int seg = b >> 2;             // 0..39
    const int quarter = b & 3;
    const float* base;
    switch (seg / NUM_T) {
        case 0:  base = Aq; break;
        case 1:  base = Bq; break;
        case 2:  base = Av; break;
        default: base = Bv; break;
    }
    const float4* p = (const float4*)(base + (seg % NUM_T) * SEG) + quarter * (SEG / 16);
    float s = 0.f;
    #pragma unroll
    for (int i = 0; i < 3; i++) {       // 3 float4 per thread, front-batched
        float4 v = __ldg(p + threadIdx.x + i * 256);
        s += v.x * v.x + v.y * v.y + v.z * v.z + v.w * v.w;
    }
    #pragma unroll
    for (int o = 16; o > 0; o >>= 1)
        s += __shfl_xor_sync(0xFFFFFFFF, s, o);
    __shared__ float red[8];
    if ((threadIdx.x & 31) == 0) red[threadIdx.x >> 5] = s;
    __syncthreads();
    if (threadIdx.x == 0) {
        float t = 0.f;
        #pragma unroll
        for (int i = 0; i < 8; i++) t += red[i];
        g_part[b] = t;
    }
}

// ---------------------------------------------------------------------------
// Kernel 2: fused prep — weff blocks FIRST so they co-schedule with convert.
//   blocks [0, NWEFF_BLOCKS):            build W_eff -> fp16 (L2-latency)
//   blocks [NWEFF_BLOCKS, +NCONV_BLOCKS): quantize X -> fp16 (HBM stream)
// ---------------------------------------------------------------------------
__global__ __launch_bounds__(256)
void k_prep1(const float* __restrict__ x,
             const float* __restrict__ Aq, const float* __restrict__ Bq,
             const float* __restrict__ Av, const float* __restrict__ Bv,
             const float* __restrict__ qkvw,
             const float* __restrict__ logits, const float* __restrict__ alpha) {
    if (blockIdx.x >= NWEFF_BLOCKS) {
        // ---- convert X: 16 floats/thread, 4 front-batched LDG.128 ----
        size_t i = ((size_t)(blockIdx.x - NWEFF_BLOCKS) * 256 + threadIdx.x) * 16;
        float4 v0 = __ldg((const float4*)(x + i));
        float4 v1 = __ldg((const float4*)(x + i + 4));
        float4 v2 = __ldg((const float4*)(x + i + 8));
        float4 v3 = __ldg((const float4*)(x + i + 12));
        uint4 h0, h1;
        h0.x = (uint32_t)__half_as_ushort(__float2half(v0.x))
             | ((uint32_t)__half_as_ushort(__float2half(v0.y)) << 16);
        h0.y = (uint32_t)__half_as_ushort(__float2half(v0.z))
             | ((uint32_t)__half_as_ushort(__float2half(v0.w)) << 16);
        h0.z = (uint32_t)__half_as_ushort(__float2half(v1.x))
             | ((uint32_t)__half_as_ushort(__float2half(v1.y)) << 16);
        h0.w = (uint32_t)__half_as_ushort(__float2half(v1.z))
             | ((uint32_t)__half_as_ushort(__float2half(v1.w)) << 16);
        h1.x = (uint32_t)__half_as_ushort(__float2half(v2.x))
             | ((uint32_t)__half_as_ushort(__float2half(v2.y)) << 16);
        h1.y = (uint32_t)__half_as_ushort(__float2half(v2.z))
             | ((uint32_t)__half_as_ushort(__float2half(v2.w)) << 16);
        h1.z = (uint32_t)__half_as_ushort(__float2half(v3.x))
             | ((uint32_t)__half_as_ushort(__float2half(v3.y)) << 16);
        h1.w = (uint32_t)__half_as_ushort(__float2half(v3.z))
             | ((uint32_t)__half_as_ushort(__float2half(v3.w)) << 16);
        *(uint4*)(g_Xh + i)     = h0;
        *(uint4*)(g_Xh + i + 8) = h1;
        return;
    }

    // ---- W_eff: 8 e-rows x 256 d-cols per block ----
    const int bid = blockIdx.x;
    const int d   = (bid % WEFF_DTILES) * 256 + threadIdx.x;
    const int e0  = (bid / WEFF_DTILES) * WEFF_EROWS;
    const int tx  = threadIdx.x;

    float acc[WEFF_EROWS];
    #pragma unroll
    for (int e = 0; e < WEFF_EROWS; e++) acc[e] = 0.f;

    bool is_q = (e0 < DIM_D);
    bool is_v = (e0 >= 2 * DIM_D);
    if (is_q || is_v) {
        __shared__ float sw[NUM_T];
        __shared__ __align__(16) float sB[NUM_T * RANK_R * WEFF_EROWS];  // [i][e]

        if (tx == 0) {
            float mx = -1e30f;
            float lg[NUM_T];
            #pragma unroll
            for (int t = 0; t < NUM_T; t++) { lg[t] = __ldg(logits + t); mx = fmaxf(mx, lg[t]); }
            float e[NUM_T], se = 0.f;
            #pragma unroll
            for (int t = 0; t < NUM_T; t++) { e[t] = expf(lg[t] - mx); se += e[t]; }
            #pragma unroll
            for (int t = 0; t < NUM_T; t++) {
                float coef = (e[t] / se) * __ldg(alpha + t);
                int sa  = is_q ? t : (20 + t);         // A-matrix segment
                int sb2 = is_q ? (10 + t) : (30 + t);  // B-matrix segment
                float ssa = g_part[4 * sa]  + g_part[4 * sa + 1]
                          + g_part[4 * sa + 2] + g_part[4 * sa + 3];
                float ssb = g_part[4 * sb2] + g_part[4 * sb2 + 1]
                          + g_part[4 * sb2 + 2] + g_part[4 * sb2 + 3];
                sw[t] = coef / (sqrtf(ssa) * sqrtf(ssb) + 1e-8f);
            }
        }
        __syncthreads();

        const float* Am = is_q ? Aq : Av;
        const float* Bm = is_q ? Bq : Bv;
        int el0 = is_q ? e0 : (e0 - 2 * DIM_D);
        for (int idx = tx; idx < NUM_T * RANK_R * WEFF_EROWS; idx += 256) {
            int i = idx >> 3, e = idx & 7;
            int t = i >> 4,  r = i & 15;
            sB[idx] = sw[t] * Bm[((size_t)t * DIM_D + el0 + e) * RANK_R + r];
        }
        __syncthreads();

        const float4* sB4 = (const float4*)sB;
        #pragma unroll 32
        for (int i = 0; i < NUM_T * RANK_R; i++) {
            float a = __ldg(Am + (size_t)i * DIM_D + d);
            float4 b0 = sB4[i * 2 + 0];
            float4 b1 = sB4[i * 2 + 1];
            acc[0] += a * b0.x;  acc[1] += a * b0.y;
            acc[2] += a * b0.z;  acc[3] += a * b0.w;
            acc[4] += a * b1.x;  acc[5] += a * b1.y;
            acc[6] += a * b1.z;  acc[7] += a * b1.w;
        }
    }
    #pragma unroll
    for (int e = 0; e < WEFF_EROWS; e++) {
        float val = qkvw[(size_t)(e0 + e) * DIM_D + d] + acc[e];
        g_Wh[(size_t)(e0 + e) * DIM_D + d] = __half_as_ushort(__float2half(val));
    }
}

// ---------------------------------------------------------------------------
// Kernel 3: HMMA GEMM  out = Xh @ Wh^T + bias   (R5 config, verbatim)
// ---------------------------------------------------------------------------
__global__ __launch_bounds__(256, 2)
void k_gemm_mma(const float* __restrict__ bias, float* __restrict__ out) {
    extern __shared__ __align__(128) char smem[];
    const uint32_t sb = smem_u32(smem);
    const int tid = threadIdx.x;
    const int lid = tid & 31;
    const int wid = tid >> 5;
    const int wm = wid & 3;          // 4 warps in M, 32 rows each
    const int wn = wid >> 2;         // 2 warps in N, 64 cols each
    const int m0 = blockIdx.y * BM;
    const int n0 = blockIdx.x * BN;

    float acc[2][8][4];
    #pragma unroll
    for (int i = 0; i < 2; i++)
        #pragma unroll
        for (int j = 0; j < 8; j++)
            #pragma unroll
            for (int q = 0; q < 4; q++) acc[i][j][q] = 0.f;

    const uint32_t a_off = (uint32_t)(lid & 15) * ROWB + (uint32_t)(lid >> 4) * 16;
    const int b_nloc = (lid < 16) ? (lid & 7) : 8 + (lid & 7);
    const uint32_t b_off = (uint32_t)b_nloc * ROWB + (uint32_t)((lid >> 3) & 1) * 16;

    auto load_stage = [&](int s) {
        uint32_t buf = sb + (uint32_t)(s % NSTAGE) * STAGEB;
        int k0 = s * BK;
        #pragma unroll
        for (int i = 0; i < 4; i++) {
            int v = tid + i * 256;
            int arr = v >> 9;            // 0: Xh, 1: Wh
            int idx = v & 511;
            int r = idx >> 2, c = idx & 3;
            uint32_t dst = buf + (uint32_t)arr * ARRB + (uint32_t)r * ROWB + (uint32_t)c * 16;
            const unsigned short* src = arr == 0
                ? g_Xh + (size_t)(m0 + r) * DIM_D + k0 + c * 8
                : g_Wh + (size_t)(n0 + r) * DIM_D + k0 + c * 8;
            CP16(dst, src);
        }
    };

    load_stage(0); CP_COMMIT();
    load_stage(1); CP_COMMIT();
    load_stage(2); CP_COMMIT();

    for (int s = 0; s < KSTAGES; s++) {
        CP_WAIT2();
        __syncthreads();
        if (s + 3 < KSTAGES) load_stage(s + 3);
        CP_COMMIT();

        uint32_t buf = sb + (uint32_t)(s % NSTAGE) * STAGEB;
        #pragma unroll
        for (int kk = 0; kk < 2; kk++) {
            uint32_t koff = (uint32_t)kk * 32;
            uint32_t ra[2][4];
            #pragma unroll
            for (int mt = 0; mt < 2; mt++)
                ldsm_x4(ra[mt], buf + (uint32_t)(wm * 32 + mt * 16) * ROWB + koff + a_off);
            #pragma unroll
            for (int half = 0; half < 2; half++) {
                uint32_t rb[2][4];
                #pragma unroll
                for (int g = 0; g < 2; g++)
                    ldsm_x4(rb[g], buf + ARRB +
                        (uint32_t)(wn * 64 + (half * 2 + g) * 16) * ROWB + koff + b_off);
                #pragma unroll
                for (int mt = 0; mt < 2; mt++)
                    #pragma unroll
                    for (int n4 = 0; n4 < 4; n4++) {
                        uint32_t b0 = rb[n4 >> 1][(n4 & 1) * 2];
                        uint32_t b1 = rb[n4 >> 1][(n4 & 1) * 2 + 1];
                        mma_fp16(acc[mt][half * 4 + n4], ra[mt], b0, b1);
                    }
            }
        }
    }

    const int r0 = m0 + wm * 32 + (lid >> 2);
    const int cb = n0 + wn * 64 + (lid & 3) * 2;
    #pragma unroll
    for (int nt = 0; nt < 8; nt++) {
        float2 bv = *(const float2*)(bias + cb + nt * 8);
        #pragma unroll
        for (int mt = 0; mt < 2; mt++) {
            int r = r0 + mt * 16;
            float2 v0 = make_float2(acc[mt][nt][0] + bv.x, acc[mt][nt][1] + bv.y);
            float2 v1 = make_float2(acc[mt][nt][2] + bv.x, acc[mt][nt][3] + bv.y);
            *(float2*)(out + (size_t)r * DIM_N + cb + nt * 8) = v0;
            *(float2*)(out + (size_t)(r + 8) * DIM_N + cb + nt * 8) = v1;
        }
    }
}

// ---------------------------------------------------------------------------
// Launch
// ---------------------------------------------------------------------------
extern "C" void kernel_launch(void* const* d_in, const int* in_sizes, int n_in,
                              void* d_out, int out_size) {
    const float* x      = (const float*)d_in[0];
    const float* Aq     = (const float*)d_in[1];
    const float* Bq     = (const float*)d_in[2];
    const float* Av     = (const float*)d_in[3];
    const float* Bv     = (const float*)d_in[4];
    const float* qkvw   = (const float*)d_in[5];
    const float* qkvb   = (const float*)d_in[6];
    const float* logits = (const float*)d_in[7];
    const float* alpha  = (const float*)d_in[8];
    float* out = (float*)d_out;

    cudaFuncSetAttribute(k_gemm_mma, cudaFuncAttributeMaxDynamicSharedMemorySize, SMEM_TOTAL);

    k_sumsq   <<<NSUMSQ_BLOCKS, 256>>>(Aq, Bq, Av, Bv);
    k_prep1   <<<NWEFF_BLOCKS + NCONV_BLOCKS, 256>>>(
                  x, Aq, Bq, Av, Bv, qkvw, logits, alpha);
    k_gemm_mma<<<dim3(DIM_N / BN, BATCH_M / BM), 256, SMEM_TOTAL>>>(qkvb, out);
}

// round 14
// speedup vs baseline: 1.2410x; 1.1737x over previous
#include <cuda_runtime.h>
#include <cuda_fp16.h>
#include <math.h>
#include <stdint.h>

// Problem constants
#define BATCH_M   16384   // B*S
#define DIM_D     768
#define DIM_N     2304    // 3*D
#define NUM_T     10
#define RANK_R    16
#define SEG       (RANK_R * DIM_D)

// GEMM tiling: CTA 128x128, 8 warps (4M x 2N), BK=32, tiled-global + bulk copy
#define BM 128
#define BN 128
#define BK 32
#define KSTAGES (DIM_D / BK)       // 24

// Tiled global layout: one tile = 128 rows x 32 fp16 = 8192 B, XOR-swizzled.
// tile_off(r, c) = r*64 + (c ^ ((r>>1)&3))*16,  r in [0,128), c in [0,4)
#define TILEB    8192
#define GSTAGE   (2 * TILEB)       // A tile + B tile per stage in SMEM
#define NSTAGE   6
#define SMEM_MB  (NSTAGE * GSTAGE) // mbarrier array offset
#define SMEM_TOTAL (SMEM_MB + 64)  // 98368 B -> 2 CTAs/SM

// sumsq: 4 partial blocks per (tensor,task) segment
#define NSUMSQ_BLOCKS 160

// fused prep: weff FIRST (overlaps convert), then convert (16 fp16/thread)
#define WEFF_DTILES  3             // 768 / 256
#define WEFF_EROWS   8
#define WEFF_ETILES  (DIM_N / WEFF_EROWS)            // 288
#define NWEFF_BLOCKS (WEFF_DTILES * WEFF_ETILES)     // 864
#define NCONV_BLOCKS 3072          // 3072 * 256 thr * 16 fp16 = X

// Device scratch (no cudaMalloc allowed)
__device__ float g_part[NSUMSQ_BLOCKS];
__device__ __align__(16) unsigned short g_Xh[(size_t)BATCH_M * DIM_D]; // tiled
__device__ __align__(16) unsigned short g_Wh[(size_t)DIM_N * DIM_D];   // tiled

// ---------------------------------------------------------------------------
// Helpers
// ---------------------------------------------------------------------------
__device__ __forceinline__ uint32_t smem_u32(const void* p) {
    uint32_t a;
    asm("{ .reg .u64 t; cvta.to.shared.u64 t, %1; cvt.u32.u64 %0, t; }" : "=r"(a) : "l"(p));
    return a;
}
#define MBAR_INIT(addr, cnt) \
    asm volatile("mbarrier.init.shared.b64 [%0], %1;" :: "r"(addr), "r"(cnt) : "memory")
#define MBAR_EXPECT_TX(addr, tx) \
    asm volatile("mbarrier.arrive.expect_tx.shared.b64 _, [%0], %1;" :: "r"(addr), "r"(tx) : "memory")
#define BULK_G2S(dst, src, nbytes, mbar) \
    asm volatile("cp.async.bulk.shared::cluster.global.mbarrier::complete_tx::bytes " \
                 "[%0], [%1], %2, [%3];" \
                 :: "r"(dst), "l"(src), "r"(nbytes), "r"(mbar) : "memory")
#define MBAR_WAIT(addr, parity) do {                                             \
    uint32_t _m = (addr); uint32_t _p = (parity); uint32_t _d;                   \
    asm volatile("{ .reg .pred p; mbarrier.try_wait.parity.acquire.cta.shared::cta.b64 p, [%1], %2; selp.b32 %0,1,0,p; }" \
        : "=r"(_d) : "r"(_m), "r"(_p) : "memory");                               \
    while (!_d) {                                                                \
        asm volatile("{ .reg .pred p; mbarrier.try_wait.parity.acquire.cta.shared::cta.b64 p, [%1], %2, 0x989680; selp.b32 %0,1,0,p; }" \
            : "=r"(_d) : "r"(_m), "r"(_p) : "memory");                           \
    }                                                                            \
} while (0)

__device__ __forceinline__ void ldsm_x4(uint32_t* r, uint32_t addr) {
    asm volatile("ldmatrix.sync.aligned.m8n8.x4.shared.b16 {%0,%1,%2,%3}, [%4];"
        : "=r"(r[0]), "=r"(r[1]), "=r"(r[2]), "=r"(r[3]) : "r"(addr));
}
__device__ __forceinline__ void mma_fp16(float* c, const uint32_t* a,
                                         uint32_t b0, uint32_t b1) {
    asm volatile("mma.sync.aligned.m16n8k16.row.col.f32.f16.f16.f32 "
        "{%0,%1,%2,%3},{%4,%5,%6,%7},{%8,%9},{%0,%1,%2,%3};"
        : "+f"(c[0]), "+f"(c[1]), "+f"(c[2]), "+f"(c[3])
        : "r"(a[0]), "r"(a[1]), "r"(a[2]), "r"(a[3]), "r"(b0), "r"(b1));
}

// ---------------------------------------------------------------------------
// Kernel 1: partial Frobenius sums. 160 blocks = 4 per (tensor,task) segment.
// ---------------------------------------------------------------------------
__global__ __launch_bounds__(256)
void k_sumsq(const float* __restrict__ Aq, const float* __restrict__ Bq,
             const float* __restrict__ Av, const float* __restrict__ Bv) {
    const int b = blockIdx.x;           // 0..159
    const int seg = b >> 2;             // 0..39
    const int quarter = b & 3;
    const float* base;
    switch (seg / NUM_T) {
        case 0:  base = Aq; break;
        case 1:  base = Bq; break;
        case 2:  base = Av; break;
        default: base = Bv; break;
    }
    const float4* p = (const float4*)(base + (seg % NUM_T) * SEG) + quarter * (SEG / 16);
    float s = 0.f;
    #pragma unroll
    for (int i = 0; i < 3; i++) {
        float4 v = __ldg(p + threadIdx.x + i * 256);
        s += v.x * v.x + v.y * v.y + v.z * v.z + v.w * v.w;
    }
    #pragma unroll
    for (int o = 16; o > 0; o >>= 1)
        s += __shfl_xor_sync(0xFFFFFFFF, s, o);
    __shared__ float red[8];
    if ((threadIdx.x & 31) == 0) red[threadIdx.x >> 5] = s;
    __syncthreads();
    if (threadIdx.x == 0) {
        float t = 0.f;
        #pragma unroll
        for (int i = 0; i < 8; i++) t += red[i];
        g_part[b] = t;
    }
}

// ---------------------------------------------------------------------------
// Kernel 2: fused prep — weff blocks FIRST so they co-schedule with convert.
// Both write the TILED global layout used by the GEMM's bulk copies.
// ---------------------------------------------------------------------------
__global__ __launch_bounds__(256)
void k_prep1(const float* __restrict__ x,
             const float* __restrict__ Aq, const float* __restrict__ Bq,
             const float* __restrict__ Av, const float* __restrict__ Bv,
             const float* __restrict__ qkvw,
             const float* __restrict__ logits, const float* __restrict__ alpha) {
    if (blockIdx.x >= NWEFF_BLOCKS) {
        // ---- convert X: 16 fp16/thread, coalesced reads, tiled 32B writes ----
        int g = (blockIdx.x - NWEFF_BLOCKS) * 256 + threadIdx.x;
        int m  = g / 48;                 // row
        int kq = g - m * 48;             // 16-fp16 quantum: k0 = kq*16
        const float* src = x + (size_t)m * DIM_D + kq * 16;
        float4 v0 = __ldg((const float4*)src);
        float4 v1 = __ldg((const float4*)src + 1);
        float4 v2 = __ldg((const float4*)src + 2);
        float4 v3 = __ldg((const float4*)src + 3);
        uint4 h0, h1;
        h0.x = (uint32_t)__half_as_ushort(__float2half(v0.x))
             | ((uint32_t)__half_as_ushort(__float2half(v0.y)) << 16);
        h0.y = (uint32_t)__half_as_ushort(__float2half(v0.z))
             | ((uint32_t)__half_as_ushort(__float2half(v0.w)) << 16);
        h0.z = (uint32_t)__half_as_ushort(__float2half(v1.x))
             | ((uint32_t)__half_as_ushort(__float2half(v1.y)) << 16);
        h0.w = (uint32_t)__half_as_ushort(__float2half(v1.z))
             | ((uint32_t)__half_as_ushort(__float2half(v1.w)) << 16);
        h1.x = (uint32_t)__half_as_ushort(__float2half(v2.x))
             | ((uint32_t)__half_as_ushort(__float2half(v2.y)) << 16);
        h1.y = (uint32_t)__half_as_ushort(__float2half(v2.z))
             | ((uint32_t)__half_as_ushort(__float2half(v2.w)) << 16);
        h1.z = (uint32_t)__half_as_ushort(__float2half(v3.x))
             | ((uint32_t)__half_as_ushort(__float2half(v3.y)) << 16);
        h1.w = (uint32_t)__half_as_ushort(__float2half(v3.z))
             | ((uint32_t)__half_as_ushort(__float2half(v3.w)) << 16);
        int mt = m >> 7, r = m & 127;
        int s  = kq >> 1, b2 = kq & 1;   // stage, 16-fp16 half within stage
        int swz = (r >> 1) & 3;
        char* tb = (char*)g_Xh + ((size_t)(mt * KSTAGES + s)) * TILEB + r * 64;
        *(uint4*)(tb + (((2 * b2)     ^ swz) * 16)) = h0;
        *(uint4*)(tb + (((2 * b2 + 1) ^ swz) * 16)) = h1;
        return;
    }

    // ---- W_eff: 8 e-rows x 256 d-cols per block, tiled output ----
    const int bid = blockIdx.x;
    const int d   = (bid % WEFF_DTILES) * 256 + threadIdx.x;
    const int e0  = (bid / WEFF_DTILES) * WEFF_EROWS;
    const int tx  = threadIdx.x;

    float acc[WEFF_EROWS];
    #pragma unroll
    for (int e = 0; e < WEFF_EROWS; e++) acc[e] = 0.f;

    bool is_q = (e0 < DIM_D);
    bool is_v = (e0 >= 2 * DIM_D);
    if (is_q || is_v) {
        __shared__ float sw[NUM_T];
        __shared__ __align__(16) float sB[NUM_T * RANK_R * WEFF_EROWS];  // [i][e]

        if (tx == 0) {
            float mx = -1e30f;
            float lg[NUM_T];
            #pragma unroll
            for (int t = 0; t < NUM_T; t++) { lg[t] = __ldg(logits + t); mx = fmaxf(mx, lg[t]); }
            float e[NUM_T], se = 0.f;
            #pragma unroll
            for (int t = 0; t < NUM_T; t++) { e[t] = expf(lg[t] - mx); se += e[t]; }
            #pragma unroll
            for (int t = 0; t < NUM_T; t++) {
                float coef = (e[t] / se) * __ldg(alpha + t);
                int sa  = is_q ? t : (20 + t);
                int sb2 = is_q ? (10 + t) : (30 + t);
                float ssa = g_part[4 * sa]  + g_part[4 * sa + 1]
                          + g_part[4 * sa + 2] + g_part[4 * sa + 3];
                float ssb = g_part[4 * sb2] + g_part[4 * sb2 + 1]
                          + g_part[4 * sb2 + 2] + g_part[4 * sb2 + 3];
                sw[t] = coef / (sqrtf(ssa) * sqrtf(ssb) + 1e-8f);
            }
        }
        __syncthreads();

        const float* Am = is_q ? Aq : Av;
        const float* Bm = is_q ? Bq : Bv;
        int el0 = is_q ? e0 : (e0 - 2 * DIM_D);
        for (int idx = tx; idx < NUM_T * RANK_R * WEFF_EROWS; idx += 256) {
            int i = idx >> 3, e = idx & 7;
            int t = i >> 4,  r = i & 15;
            sB[idx] = sw[t] * Bm[((size_t)t * DIM_D + el0 + e) * RANK_R + r];
        }
        __syncthreads();

        const float4* sB4 = (const float4*)sB;
        #pragma unroll 32
        for (int i = 0; i < NUM_T * RANK_R; i++) {
            float a = __ldg(Am + (size_t)i * DIM_D + d);
            float4 b0 = sB4[i * 2 + 0];
            float4 b1 = sB4[i * 2 + 1];
            acc[0] += a * b0.x;  acc[1] += a * b0.y;
            acc[2] += a * b0.z;  acc[3] += a * b0.w;
            acc[4] += a * b1.x;  acc[5] += a * b1.y;
            acc[6] += a * b1.z;  acc[7] += a * b1.w;
        }
    }
    // tiled store: nt = e0>>7, stage = d>>5, chunk = (d>>3)&3, byte = (d&7)*2
    {
        int nt = e0 >> 7;
        int s  = d >> 5;
        int c  = (d >> 3) & 3;
        int bo = (d & 7) * 2;
        char* tb = (char*)g_Wh + ((size_t)(nt * KSTAGES + s)) * TILEB;
        #pragma unroll
        for (int e = 0; e < WEFF_EROWS; e++) {
            float val = qkvw[(size_t)(e0 + e) * DIM_D + d] + acc[e];
            int r = (e0 + e) & 127;
            int swz = (r >> 1) & 3;
            *(unsigned short*)(tb + r * 64 + ((c ^ swz) * 16) + bo) =
                __half_as_ushort(__float2half(val));
        }
    }
}

// ---------------------------------------------------------------------------
// Kernel 3: HMMA GEMM  out = Xh @ Wh^T + bias
//   Tiled-global sources; per-stage load = 2 cp.async.bulk + mbarrier.
//   6-stage ring, depth-5 prefetch, 2 CTAs/SM.
// ---------------------------------------------------------------------------
__global__ __launch_bounds__(256, 2)
void k_gemm_mma(const float* __restrict__ bias, float* __restrict__ out) {
    extern __shared__ __align__(1024) char smem[];
    const uint32_t sb = smem_u32(smem);
    const uint32_t mb = sb + SMEM_MB;
    const int tid = threadIdx.x;
    const int lid = tid & 31;
    const int wid = tid >> 5;
    const int wm = wid & 3;          // 4 warps in M, 32 rows each
    const int wn = wid >> 2;         // 2 warps in N, 64 cols each
    const int m0 = blockIdx.y * BM;
    const int n0 = blockIdx.x * BN;

    if (tid == 0) {
        #pragma unroll
        for (int j = 0; j < NSTAGE; j++) MBAR_INIT(mb + j * 8, 1);
    }
    __syncthreads();

    const char* srcA = (const char*)g_Xh + (size_t)blockIdx.y * (KSTAGES * TILEB);
    const char* srcB = (const char*)g_Wh + (size_t)blockIdx.x * (KSTAGES * TILEB);

    auto issue = [&](int s) {
        uint32_t m = mb + (uint32_t)(s % NSTAGE) * 8;
        uint32_t dA = sb + (uint32_t)(s % NSTAGE) * GSTAGE;
        MBAR_EXPECT_TX(m, GSTAGE);
        BULK_G2S(dA,         srcA + (size_t)s * TILEB, TILEB, m);
        BULK_G2S(dA + TILEB, srcB + (size_t)s * TILEB, TILEB, m);
    };

    if (tid == 0) {
        for (int s = 0; s < 5; s++) issue(s);
    }

    float acc[2][8][4];
    #pragma unroll
    for (int i = 0; i < 2; i++)
        #pragma unroll
        for (int j = 0; j < 8; j++)
            #pragma unroll
            for (int q = 0; q < 4; q++) acc[i][j][q] = 0.f;

    // per-lane constants (swizzle matches writer: c' = c ^ ((r>>1)&3))
    const int aRow  = wm * 32 + (lid & 15);
    const int aSwz  = ((lid & 15) >> 1) & 3;
    const int aCh   = lid >> 4;                       // 0/1
    const int bRow  = (lid < 16) ? (lid & 7) : 8 + (lid & 7);
    const int bSwz  = (bRow >> 1) & 3;
    const int bCh   = (lid >> 3) & 1;                 // 0/1

    for (int s = 0; s < KSTAGES; s++) {
        MBAR_WAIT(mb + (uint32_t)(s % NSTAGE) * 8, (s / NSTAGE) & 1);
        __syncthreads();                  // all warps done with stage s-1
        if (tid == 0 && s + 5 < KSTAGES) issue(s + 5);

        uint32_t bufA = sb + (uint32_t)(s % NSTAGE) * GSTAGE;
        uint32_t bufB = bufA + TILEB;
        #pragma unroll
        for (int kk = 0; kk < 2; kk++) {
            uint32_t cA = (uint32_t)(((kk * 2 + aCh) ^ aSwz) * 16);
            uint32_t ra[2][4];
            #pragma unroll
            for (int mt = 0; mt < 2; mt++)
                ldsm_x4(ra[mt], bufA + (uint32_t)(aRow + mt * 16) * 64 + cA);
            uint32_t cB = (uint32_t)(((kk * 2 + bCh) ^ bSwz) * 16);
            #pragma unroll
            for (int half = 0; half < 2; half++) {
                uint32_t rb[2][4];
                #pragma unroll
                for (int g = 0; g < 2; g++)
                    ldsm_x4(rb[g], bufB +
                        (uint32_t)(wn * 64 + (half * 2 + g) * 16 + bRow) * 64 + cB);
                #pragma unroll
                for (int mt = 0; mt < 2; mt++)
                    #pragma unroll
                    for (int n4 = 0; n4 < 4; n4++) {
                        uint32_t b0 = rb[n4 >> 1][(n4 & 1) * 2];
                        uint32_t b1 = rb[n4 >> 1][(n4 & 1) * 2 + 1];
                        mma_fp16(acc[mt][half * 4 + n4], ra[mt], b0, b1);
                    }
            }
        }
    }

    // Epilogue: bias add + float2 stores
    const int r0 = m0 + wm * 32 + (lid >> 2);
    const int cb = n0 + wn * 64 + (lid & 3) * 2;
    #pragma unroll
    for (int nt = 0; nt < 8; nt++) {
        float2 bv = *(const float2*)(bias + cb + nt * 8);
        #pragma unroll
        for (int mt = 0; mt < 2; mt++) {
            int r = r0 + mt * 16;
            float2 v0 = make_float2(acc[mt][nt][0] + bv.x, acc[mt][nt][1] + bv.y);
            float2 v1 = make_float2(acc[mt][nt][2] + bv.x, acc[mt][nt][3] + bv.y);
            *(float2*)(out + (size_t)r * DIM_N + cb + nt * 8) = v0;
            *(float2*)(out + (size_t)(r + 8) * DIM_N + cb + nt * 8) = v1;
        }
    }
}

// ---------------------------------------------------------------------------
// Launch
// ---------------------------------------------------------------------------
extern "C" void kernel_launch(void* const* d_in, const int* in_sizes, int n_in,
                              void* d_out, int out_size) {
    const float* x      = (const float*)d_in[0];
    const float* Aq     = (const float*)d_in[1];
    const float* Bq     = (const float*)d_in[2];
    const float* Av     = (const float*)d_in[3];
    const float* Bv     = (const float*)d_in[4];
    const float* qkvw   = (const float*)d_in[5];
    const float* qkvb   = (const float*)d_in[6];
    const float* logits = (const float*)d_in[7];
    const float* alpha  = (const float*)d_in[8];
    float* out = (float*)d_out;

    cudaFuncSetAttribute(k_gemm_mma, cudaFuncAttributeMaxDynamicSharedMemorySize, SMEM_TOTAL);

    k_sumsq   <<<NSUMSQ_BLOCKS, 256>>>(Aq, Bq, Av, Bv);
    k_prep1   <<<NWEFF_BLOCKS + NCONV_BLOCKS, 256>>>(
                  x, Aq, Bq, Av, Bv, qkvw, logits, alpha);
    k_gemm_mma<<<dim3(DIM_N / BN, BATCH_M / BM), 256, SMEM_TOTAL>>>(qkvb, out);
}

// round 15
// speedup vs baseline: 1.3621x; 1.0976x over previous
#include <cuda_runtime.h>
#include <cuda_fp16.h>
#include <math.h>
#include <stdint.h>

// Problem constants
#define BATCH_M   16384   // B*S
#define DIM_D     768
#define DIM_N     2304    // 3*D
#define NUM_T     10
#define RANK_R    16
#define SEG       (RANK_R * DIM_D)

// GEMM tiling: CTA 128x128, 8 warps (4M x 2N), tiled-global + bulk copy.
// Global tile = 128 rows x 32 fp16 = 8192 B, XOR-swizzled:
//   tile_off(r, c) = r*64 + (c ^ ((r>>1)&3))*16,  r in [0,128), c in [0,4)
#define BM 128
#define BN 128
#define KTILES    24               // K tiles of 32 fp16 (768/32)
#define TILEB     8192
// One pipeline stage = 2 consecutive K tiles (BK=64): A 16KB + B 16KB.
#define NOUTER    12               // 24 tiles / 2 per stage
#define GSTAGE    (4 * TILEB)      // 32768
#define NSTAGE    3
#define SMEM_MB   (NSTAGE * GSTAGE)     // 98304
#define SMEM_TOTAL (SMEM_MB + 64)       // 98368 -> 2 CTAs/SM

// sumsq: 4 partial blocks per (tensor,task) segment
#define NSUMSQ_BLOCKS 160

// fused prep: weff FIRST (overlaps convert), then convert (16 fp16/thread)
#define WEFF_DTILES  3             // 768 / 256
#define WEFF_EROWS   8
#define WEFF_ETILES  (DIM_N / WEFF_EROWS)            // 288
#define NWEFF_BLOCKS (WEFF_DTILES * WEFF_ETILES)     // 864
#define NCONV_BLOCKS 3072          // 3072 * 256 thr * 16 fp16 = X

// Device scratch (no cudaMalloc allowed)
__device__ float g_part[NSUMSQ_BLOCKS];
__device__ __align__(16) unsigned short g_Xh[(size_t)BATCH_M * DIM_D]; // tiled
__device__ __align__(16) unsigned short g_Wh[(size_t)DIM_N * DIM_D];   // tiled

// ---------------------------------------------------------------------------
// Helpers
// ---------------------------------------------------------------------------
__device__ __forceinline__ uint32_t smem_u32(const void* p) {
    uint32_t a;
    asm("{ .reg .u64 t; cvta.to.shared.u64 t, %1; cvt.u32.u64 %0, t; }" : "=r"(a) : "l"(p));
    return a;
}
#define MBAR_INIT(addr, cnt) \
    asm volatile("mbarrier.init.shared.b64 [%0], %1;" :: "r"(addr), "r"(cnt) : "memory")
#define MBAR_EXPECT_TX(addr, tx) \
    asm volatile("mbarrier.arrive.expect_tx.shared.b64 _, [%0], %1;" :: "r"(addr), "r"(tx) : "memory")
#define BULK_G2S(dst, src, nbytes, mbar) \
    asm volatile("cp.async.bulk.shared::cluster.global.mbarrier::complete_tx::bytes " \
                 "[%0], [%1], %2, [%3];" \
                 :: "r"(dst), "l"(src), "r"(nbytes), "r"(mbar) : "memory")
#define MBAR_WAIT(addr, parity) do {                                             \
    uint32_t _m = (addr); uint32_t _p = (parity); uint32_t _d;                   \
    asm volatile("{ .reg .pred p; mbarrier.try_wait.parity.acquire.cta.shared::cta.b64 p, [%1], %2; selp.b32 %0,1,0,p; }" \
        : "=r"(_d) : "r"(_m), "r"(_p) : "memory");                               \
    while (!_d) {                                                                \
        asm volatile("{ .reg .pred p; mbarrier.try_wait.parity.acquire.cta.shared::cta.b64 p, [%1], %2, 0x989680; selp.b32 %0,1,0,p; }" \
            : "=r"(_d) : "r"(_m), "r"(_p) : "memory");                           \
    }                                                                            \
} while (0)

__device__ __forceinline__ void ldsm_x4(uint32_t* r, uint32_t addr) {
    asm volatile("ldmatrix.sync.aligned.m8n8.x4.shared.b16 {%0,%1,%2,%3}, [%4];"
        : "=r"(r[0]), "=r"(r[1]), "=r"(r[2]), "=r"(r[3]) : "r"(addr));
}
__device__ __forceinline__ void mma_fp16(float* c, const uint32_t* a,
                                         uint32_t b0, uint32_t b1) {
    asm volatile("mma.sync.aligned.m16n8k16.row.col.f32.f16.f16.f32 "
        "{%0,%1,%2,%3},{%4,%5,%6,%7},{%8,%9},{%0,%1,%2,%3};"
        : "+f"(c[0]), "+f"(c[1]), "+f"(c[2]), "+f"(c[3])
        : "r"(a[0]), "r"(a[1]), "r"(a[2]), "r"(a[3]), "r"(b0), "r"(b1));
}

// ---------------------------------------------------------------------------
// Kernel 1: partial Frobenius sums. 160 blocks = 4 per (tensor,task) segment.
// ---------------------------------------------------------------------------
__global__ __launch_bounds__(256)
void k_sumsq(const float* __restrict__ Aq, const float* __restrict__ Bq,
             const float* __restrict__ Av, const float* __restrict__ Bv) {
    const int b = blockIdx.x;           // 0..159
    const int seg = b >> 2;             // 0..39
    const int quarter = b & 3;
    const float* base;
    switch (seg / NUM_T) {
        case 0:  base = Aq; break;
        case 1:  base = Bq; break;
        case 2:  base = Av; break;
        default: base = Bv; break;
    }
    const float4* p = (const float4*)(base + (seg % NUM_T) * SEG) + quarter * (SEG / 16);
    float s = 0.f;
    #pragma unroll
    for (int i = 0; i < 3; i++) {
        float4 v = __ldg(p + threadIdx.x + i * 256);
        s += v.x * v.x + v.y * v.y + v.z * v.z + v.w * v.w;
    }
    #pragma unroll
    for (int o = 16; o > 0; o >>= 1)
        s += __shfl_xor_sync(0xFFFFFFFF, s, o);
    __shared__ float red[8];
    if ((threadIdx.x & 31) == 0) red[threadIdx.x >> 5] = s;
    __syncthreads();
    if (threadIdx.x == 0) {
        float t = 0.f;
        #pragma unroll
        for (int i = 0; i < 8; i++) t += red[i];
        g_part[b] = t;
    }
}

// ---------------------------------------------------------------------------
// Kernel 2: fused prep — weff blocks FIRST so they co-schedule with convert.
// Both write the TILED global layout used by the GEMM's bulk copies.
// ---------------------------------------------------------------------------
__global__ __launch_bounds__(256)
void k_prep1(const float* __restrict__ x,
             const float* __restrict__ Aq, const float* __restrict__ Bq,
             const float* __restrict__ Av, const float* __restrict__ Bv,
             const float* __restrict__ qkvw,
             const float* __restrict__ logits, const float* __restrict__ alpha) {
    if (blockIdx.x >= NWEFF_BLOCKS) {
        // ---- convert X: 16 fp16/thread, coalesced reads, tiled 32B writes ----
        int g = (blockIdx.x - NWEFF_BLOCKS) * 256 + threadIdx.x;
        int m  = g / 48;                 // row
        int kq = g - m * 48;             // 16-fp16 quantum: k0 = kq*16
        const float* src = x + (size_t)m * DIM_D + kq * 16;
        float4 v0 = __ldg((const float4*)src);
        float4 v1 = __ldg((const float4*)src + 1);
        float4 v2 = __ldg((const float4*)src + 2);
        float4 v3 = __ldg((const float4*)src + 3);
        uint4 h0, h1;
        h0.x = (uint32_t)__half_as_ushort(__float2half(v0.x))
             | ((uint32_t)__half_as_ushort(__float2half(v0.y)) << 16);
        h0.y = (uint32_t)__half_as_ushort(__float2half(v0.z))
             | ((uint32_t)__half_as_ushort(__float2half(v0.w)) << 16);
        h0.z = (uint32_t)__half_as_ushort(__float2half(v1.x))
             | ((uint32_t)__half_as_ushort(__float2half(v1.y)) << 16);
        h0.w = (uint32_t)__half_as_ushort(__float2half(v1.z))
             | ((uint32_t)__half_as_ushort(__float2half(v1.w)) << 16);
        h1.x = (uint32_t)__half_as_ushort(__float2half(v2.x))
             | ((uint32_t)__half_as_ushort(__float2half(v2.y)) << 16);
        h1.y = (uint32_t)__half_as_ushort(__float2half(v2.z))
             | ((uint32_t)__half_as_ushort(__float2half(v2.w)) << 16);
        h1.z = (uint32_t)__half_as_ushort(__float2half(v3.x))
             | ((uint32_t)__half_as_ushort(__float2half(v3.y)) << 16);
        h1.w = (uint32_t)__half_as_ushort(__float2half(v3.z))
             | ((uint32_t)__half_as_ushort(__float2half(v3.w)) << 16);
        int mt = m >> 7, r = m & 127;
        int s  = kq >> 1, b2 = kq & 1;   // K-tile, 16-fp16 half within tile
        int swz = (r >> 1) & 3;
        char* tb = (char*)g_Xh + ((size_t)(mt * KTILES + s)) * TILEB + r * 64;
        *(uint4*)(tb + (((2 * b2)     ^ swz) * 16)) = h0;
        *(uint4*)(tb + (((2 * b2 + 1) ^ swz) * 16)) = h1;
        return;
    }

    // ---- W_eff: 8 e-rows x 256 d-cols per block, tiled output ----
    const int bid = blockIdx.x;
    const int d   = (bid % WEFF_DTILES) * 256 + threadIdx.x;
    const int e0  = (bid / WEFF_DTILES) * WEFF_EROWS;
    const int tx  = threadIdx.x;

    float acc[WEFF_EROWS];
    #pragma unroll
    for (int e = 0; e < WEFF_EROWS; e++) acc[e] = 0.f;

    bool is_q = (e0 < DIM_D);
    bool is_v = (e0 >= 2 * DIM_D);
    if (is_q || is_v) {
        __shared__ float sw[NUM_T];
        __shared__ __align__(16) float sB[NUM_T * RANK_R * WEFF_EROWS];  // [i][e]

        if (tx == 0) {
            float mx = -1e30f;
            float lg[NUM_T];
            #pragma unroll
            for (int t = 0; t < NUM_T; t++) { lg[t] = __ldg(logits + t); mx = fmaxf(mx, lg[t]); }
            float e[NUM_T], se = 0.f;
            #pragma unroll
            for (int t = 0; t < NUM_T; t++) { e[t] = expf(lg[t] - mx); se += e[t]; }
            #pragma unroll
            for (int t = 0; t < NUM_T; t++) {
                float coef = (e[t] / se) * __ldg(alpha + t);
                int sa  = is_q ? t : (20 + t);
                int sb2 = is_q ? (10 + t) : (30 + t);
                float ssa = g_part[4 * sa]  + g_part[4 * sa + 1]
                          + g_part[4 * sa + 2] + g_part[4 * sa + 3];
                float ssb = g_part[4 * sb2] + g_part[4 * sb2 + 1]
                          + g_part[4 * sb2 + 2] + g_part[4 * sb2 + 3];
                sw[t] = coef / (sqrtf(ssa) * sqrtf(ssb) + 1e-8f);
            }
        }
        __syncthreads();

        const float* Am = is_q ? Aq : Av;
        const float* Bm = is_q ? Bq : Bv;
        int el0 = is_q ? e0 : (e0 - 2 * DIM_D);
        for (int idx = tx; idx < NUM_T * RANK_R * WEFF_EROWS; idx += 256) {
            int i = idx >> 3, e = idx & 7;
            int t = i >> 4,  r = i & 15;
            sB[idx] = sw[t] * Bm[((size_t)t * DIM_D + el0 + e) * RANK_R + r];
        }
        __syncthreads();

        const float4* sB4 = (const float4*)sB;
        #pragma unroll 32
        for (int i = 0; i < NUM_T * RANK_R; i++) {
            float a = __ldg(Am + (size_t)i * DIM_D + d);
            float4 b0 = sB4[i * 2 + 0];
            float4 b1 = sB4[i * 2 + 1];
            acc[0] += a * b0.x;  acc[1] += a * b0.y;
            acc[2] += a * b0.z;  acc[3] += a * b0.w;
            acc[4] += a * b1.x;  acc[5] += a * b1.y;
            acc[6] += a * b1.z;  acc[7] += a * b1.w;
        }
    }
    // tiled store: nt = e0>>7, K-tile = d>>5, chunk = (d>>3)&3, byte = (d&7)*2
    {
        int nt = e0 >> 7;
        int s  = d >> 5;
        int c  = (d >> 3) & 3;
        int bo = (d & 7) * 2;
        char* tb = (char*)g_Wh + ((size_t)(nt * KTILES + s)) * TILEB;
        #pragma unroll
        for (int e = 0; e < WEFF_EROWS; e++) {
            float val = qkvw[(size_t)(e0 + e) * DIM_D + d] + acc[e];
            int r = (e0 + e) & 127;
            int swz = (r >> 1) & 3;
            *(unsigned short*)(tb + r * 64 + ((c ^ swz) * 16) + bo) =
                __half_as_ushort(__float2half(val));
        }
    }
}

// ---------------------------------------------------------------------------
// Kernel 3: HMMA GEMM  out = Xh @ Wh^T + bias
//   BK=64 stage = 2 contiguous K tiles; per-stage load = 2 bulk copies
//   of 16KB + 1 mbarrier. 3-stage ring, depth-2 prefetch, 2 CTAs/SM.
// ---------------------------------------------------------------------------
__global__ __launch_bounds__(256, 2)
void k_gemm_mma(const float* __restrict__ bias, float* __restrict__ out) {
    extern __shared__ __align__(1024) char smem[];
    const uint32_t sb = smem_u32(smem);
    const uint32_t mb = sb + SMEM_MB;
    const int tid = threadIdx.x;
    const int lid = tid & 31;
    const int wid = tid >> 5;
    const int wm = wid & 3;          // 4 warps in M, 32 rows each
    const int wn = wid >> 2;         // 2 warps in N, 64 cols each
    const int m0 = blockIdx.y * BM;
    const int n0 = blockIdx.x * BN;

    if (tid == 0) {
        #pragma unroll
        for (int j = 0; j < NSTAGE; j++) MBAR_INIT(mb + j * 8, 1);
    }
    __syncthreads();

    const char* srcA = (const char*)g_Xh + (size_t)blockIdx.y * (KTILES * TILEB);
    const char* srcB = (const char*)g_Wh + (size_t)blockIdx.x * (KTILES * TILEB);

    // Stage s covers K tiles 2s and 2s+1 (contiguous 16KB in tiled global).
    auto issue = [&](int s) {
        uint32_t m = mb + (uint32_t)(s % NSTAGE) * 8;
        uint32_t dst = sb + (uint32_t)(s % NSTAGE) * GSTAGE;
        MBAR_EXPECT_TX(m, GSTAGE);
        BULK_G2S(dst,             srcA + (size_t)s * 2 * TILEB, 2 * TILEB, m);
        BULK_G2S(dst + 2 * TILEB, srcB + (size_t)s * 2 * TILEB, 2 * TILEB, m);
    };

    if (tid == 0) { issue(0); issue(1); }

    float acc[2][8][4];
    #pragma unroll
    for (int i = 0; i < 2; i++)
        #pragma unroll
        for (int j = 0; j < 8; j++)
            #pragma unroll
            for (int q = 0; q < 4; q++) acc[i][j][q] = 0.f;

    // per-lane constants (swizzle matches writer: c' = c ^ ((r>>1)&3))
    const int aRow  = wm * 32 + (lid & 15);
    const int aSwz  = ((lid & 15) >> 1) & 3;
    const int aCh   = lid >> 4;                       // 0/1
    const int bRow  = (lid < 16) ? (lid & 7) : 8 + (lid & 7);
    const int bSwz  = (bRow >> 1) & 3;
    const int bCh   = (lid >> 3) & 1;                 // 0/1

    for (int s = 0; s < NOUTER; s++) {
        MBAR_WAIT(mb + (uint32_t)(s % NSTAGE) * 8, (s / NSTAGE) & 1);
        __syncthreads();                  // all warps done with stage s-1
        if (tid == 0 && s + 2 < NOUTER) issue(s + 2);

        uint32_t stage = sb + (uint32_t)(s % NSTAGE) * GSTAGE;
        #pragma unroll
        for (int kt = 0; kt < 2; kt++) {
            uint32_t bufA = stage + (uint32_t)kt * TILEB;
            uint32_t bufB = stage + 2 * TILEB + (uint32_t)kt * TILEB;
            #pragma unroll
            for (int kk = 0; kk < 2; kk++) {
                uint32_t cA = (uint32_t)(((kk * 2 + aCh) ^ aSwz) * 16);
                uint32_t ra[2][4];
                #pragma unroll
                for (int mt = 0; mt < 2; mt++)
                    ldsm_x4(ra[mt], bufA + (uint32_t)(aRow + mt * 16) * 64 + cA);
                uint32_t cB = (uint32_t)(((kk * 2 + bCh) ^ bSwz) * 16);
                #pragma unroll
                for (int half = 0; half < 2; half++) {
                    uint32_t rb[2][4];
                    #pragma unroll
                    for (int g = 0; g < 2; g++)
                        ldsm_x4(rb[g], bufB +
                            (uint32_t)(wn * 64 + (half * 2 + g) * 16 + bRow) * 64 + cB);
                    #pragma unroll
                    for (int mt = 0; mt < 2; mt++)
                        #pragma unroll
                        for (int n4 = 0; n4 < 4; n4++) {
                            uint32_t b0 = rb[n4 >> 1][(n4 & 1) * 2];
                            uint32_t b1 = rb[n4 >> 1][(n4 & 1) * 2 + 1];
                            mma_fp16(acc[mt][half * 4 + n4], ra[mt], b0, b1);
                        }
                }
            }
        }
    }

    // Epilogue: bias add + float2 stores
    const int r0 = m0 + wm * 32 + (lid >> 2);
    const int cb = n0 + wn * 64 + (lid & 3) * 2;
    #pragma unroll
    for (int nt = 0; nt < 8; nt++) {
        float2 bv = *(const float2*)(bias + cb + nt * 8);
        #pragma unroll
        for (int mt = 0; mt < 2; mt++) {
            int r = r0 + mt * 16;
            float2 v0 = make_float2(acc[mt][nt][0] + bv.x, acc[mt][nt][1] + bv.y);
            float2 v1 = make_float2(acc[mt][nt][2] + bv.x, acc[mt][nt][3] + bv.y);
            *(float2*)(out + (size_t)r * DIM_N + cb + nt * 8) = v0;
            *(float2*)(out + (size_t)(r + 8) * DIM_N + cb + nt * 8) = v1;
        }
    }
}

// ---------------------------------------------------------------------------
// Launch
// ---------------------------------------------------------------------------
extern "C" void kernel_launch(void* const* d_in, const int* in_sizes, int n_in,
                              void* d_out, int out_size) {
    const float* x      = (const float*)d_in[0];
    const float* Aq     = (const float*)d_in[1];
    const float* Bq     = (const float*)d_in[2];
    const float* Av     = (const float*)d_in[3];
    const float* Bv     = (const float*)d_in[4];
    const float* qkvw   = (const float*)d_in[5];
    const float* qkvb   = (const float*)d_in[6];
    const float* logits = (const float*)d_in[7];
    const float* alpha  = (const float*)d_in[8];
    float* out = (float*)d_out;

    cudaFuncSetAttribute(k_gemm_mma, cudaFuncAttributeMaxDynamicSharedMemorySize, SMEM_TOTAL);

    k_sumsq   <<<NSUMSQ_BLOCKS, 256>>>(Aq, Bq, Av, Bv);
    k_prep1   <<<NWEFF_BLOCKS + NCONV_BLOCKS, 256>>>(
                  x, Aq, Bq, Av, Bv, qkvw, logits, alpha);
    k_gemm_mma<<<dim3(DIM_N / BN, BATCH_M / BM), 256, SMEM_TOTAL>>>(qkvb, out);
}

// round 16
// speedup vs baseline: 1.3641x; 1.0014x over previous
#include <cuda_runtime.h>
#include <cuda_fp16.h>
#include <math.h>
#include <stdint.h>

// Problem constants
#define BATCH_M   16384   // B*S
#define DIM_D     768
#define DIM_N     2304    // 3*D
#define NUM_T     10
#define RANK_R    16
#define SEG       (RANK_R * DIM_D)

// GEMM tiling: CTA 128x128, 8 warps (4M x 2N), tiled-global + bulk copy.
// Global tile = 128 rows x 32 fp16 = 8192 B, XOR-swizzled:
//   tile_off(r, c) = r*64 + (c ^ ((r>>1)&3))*16,  r in [0,128), c in [0,4)
#define BM 128
#define BN 128
#define KTILES    24               // K tiles of 32 fp16 (768/32)
#define TILEB     8192
#define SPT       12               // pipeline stages per output tile (BK=64)
#define GSTAGE    (4 * TILEB)      // 32768 per stage (A 16KB + B 16KB)
#define NSTAGE    3
#define SMEM_MB   (NSTAGE * GSTAGE)     // 98304
#define SMEM_TOTAL (SMEM_MB + 64)       // 98368 -> 2 CTAs/SM

// Persistent grid
#define NTILE_N   (DIM_N / BN)     // 18
#define NTILE_M   (BATCH_M / BM)   // 128
#define NTILES    (NTILE_N * NTILE_M)   // 2304
#define NPERS     304              // 2 CTAs x 152 SMs

// sumsq: 4 partial blocks per (tensor,task) segment
#define NSUMSQ_BLOCKS 160

// fused prep: weff FIRST (overlaps convert), then convert (16 fp16/thread)
#define WEFF_DTILES  3             // 768 / 256
#define WEFF_EROWS   8
#define WEFF_ETILES  (DIM_N / WEFF_EROWS)            // 288
#define NWEFF_BLOCKS (WEFF_DTILES * WEFF_ETILES)     // 864
#define NCONV_BLOCKS 3072          // 3072 * 256 thr * 16 fp16 = X

// Device scratch (no cudaMalloc allowed)
__device__ float g_part[NSUMSQ_BLOCKS];
__device__ __align__(16) unsigned short g_Xh[(size_t)BATCH_M * DIM_D]; // tiled
__device__ __align__(16) unsigned short g_Wh[(size_t)DIM_N * DIM_D];   // tiled

// ---------------------------------------------------------------------------
// Helpers
// ---------------------------------------------------------------------------
__device__ __forceinline__ uint32_t smem_u32(const void* p) {
    uint32_t a;
    asm("{ .reg .u64 t; cvta.to.shared.u64 t, %1; cvt.u32.u64 %0, t; }" : "=r"(a) : "l"(p));
    return a;
}
#define MBAR_INIT(addr, cnt) \
    asm volatile("mbarrier.init.shared.b64 [%0], %1;" :: "r"(addr), "r"(cnt) : "memory")
#define MBAR_EXPECT_TX(addr, tx) \
    asm volatile("mbarrier.arrive.expect_tx.shared.b64 _, [%0], %1;" :: "r"(addr), "r"(tx) : "memory")
#define BULK_G2S(dst, src, nbytes, mbar) \
    asm volatile("cp.async.bulk.shared::cluster.global.mbarrier::complete_tx::bytes " \
                 "[%0], [%1], %2, [%3];" \
                 :: "r"(dst), "l"(src), "r"(nbytes), "r"(mbar) : "memory")
#define MBAR_WAIT(addr, parity) do {                                             \
    uint32_t _m = (addr); uint32_t _p = (parity); uint32_t _d;                   \
    asm volatile("{ .reg .pred p; mbarrier.try_wait.parity.acquire.cta.shared::cta.b64 p, [%1], %2; selp.b32 %0,1,0,p; }" \
        : "=r"(_d) : "r"(_m), "r"(_p) : "memory");                               \
    while (!_d) {                                                                \
        asm volatile("{ .reg .pred p; mbarrier.try_wait.parity.acquire.cta.shared::cta.b64 p, [%1], %2, 0x989680; selp.b32 %0,1,0,p; }" \
            : "=r"(_d) : "r"(_m), "r"(_p) : "memory");                           \
    }                                                                            \
} while (0)

__device__ __forceinline__ void ldsm_x4(uint32_t* r, uint32_t addr) {
    asm volatile("ldmatrix.sync.aligned.m8n8.x4.shared.b16 {%0,%1,%2,%3}, [%4];"
        : "=r"(r[0]), "=r"(r[1]), "=r"(r[2]), "=r"(r[3]) : "r"(addr));
}
__device__ __forceinline__ void mma_fp16(float* c, const uint32_t* a,
                                         uint32_t b0, uint32_t b1) {
    asm volatile("mma.sync.aligned.m16n8k16.row.col.f32.f16.f16.f32 "
        "{%0,%1,%2,%3},{%4,%5,%6,%7},{%8,%9},{%0,%1,%2,%3};"
        : "+f"(c[0]), "+f"(c[1]), "+f"(c[2]), "+f"(c[3])
        : "r"(a[0]), "r"(a[1]), "r"(a[2]), "r"(a[3]), "r"(b0), "r"(b1));
}

// ---------------------------------------------------------------------------
// Kernel 1: partial Frobenius sums. 160 blocks = 4 per (tensor,task) segment.
// ---------------------------------------------------------------------------
__global__ __launch_bounds__(256)
void k_sumsq(const float* __restrict__ Aq, const float* __restrict__ Bq,
             const float* __restrict__ Av, const float* __restrict__ Bv) {
    const int b = blockIdx.x;           // 0..159
    const int seg = b >> 2;             // 0..39
    const int quarter = b & 3;
    const float* base;
    switch (seg / NUM_T) {
        case 0:  base = Aq; break;
        case 1:  base = Bq; break;
        case 2:  base = Av; break;
        default: base = Bv; break;
    }
    const float4* p = (const float4*)(base + (seg % NUM_T) * SEG) + quarter * (SEG / 16);
    float s = 0.f;
    #pragma unroll
    for (int i = 0; i < 3; i++) {
        float4 v = __ldg(p + threadIdx.x + i * 256);
        s += v.x * v.x + v.y * v.y + v.z * v.z + v.w * v.w;
    }
    #pragma unroll
    for (int o = 16; o > 0; o >>= 1)
        s += __shfl_xor_sync(0xFFFFFFFF, s, o);
    __shared__ float red[8];
    if ((threadIdx.x & 31) == 0) red[threadIdx.x >> 5] = s;
    __syncthreads();
    if (threadIdx.x == 0) {
        float t = 0.f;
        #pragma unroll
        for (int i = 0; i < 8; i++) t += red[i];
        g_part[b] = t;
    }
}

// ---------------------------------------------------------------------------
// Kernel 2: fused prep — weff blocks FIRST so they co-schedule with convert.
// Both write the TILED global layout used by the GEMM's bulk copies.
// ---------------------------------------------------------------------------
__global__ __launch_bounds__(256)
void k_prep1(const float* __restrict__ x,
             const float* __restrict__ Aq, const float* __restrict__ Bq,
             const float* __restrict__ Av, const float* __restrict__ Bv,
             const float* __restrict__ qkvw,
             const float* __restrict__ logits, const float* __restrict__ alpha) {
    if (blockIdx.x >= NWEFF_BLOCKS) {
        // ---- convert X: 16 fp16/thread, coalesced reads, tiled 32B writes ----
        int g = (blockIdx.x - NWEFF_BLOCKS) * 256 + threadIdx.x;
        int m  = g / 48;                 // row
        int kq = g - m * 48;             // 16-fp16 quantum: k0 = kq*16
        const float* src = x + (size_t)m * DIM_D + kq * 16;
        float4 v0 = __ldg((const float4*)src);
        float4 v1 = __ldg((const float4*)src + 1);
        float4 v2 = __ldg((const float4*)src + 2);
        float4 v3 = __ldg((const float4*)src + 3);
        uint4 h0, h1;
        h0.x = (uint32_t)__half_as_ushort(__float2half(v0.x))
             | ((uint32_t)__half_as_ushort(__float2half(v0.y)) << 16);
        h0.y = (uint32_t)__half_as_ushort(__float2half(v0.z))
             | ((uint32_t)__half_as_ushort(__float2half(v0.w)) << 16);
        h0.z = (uint32_t)__half_as_ushort(__float2half(v1.x))
             | ((uint32_t)__half_as_ushort(__float2half(v1.y)) << 16);
        h0.w = (uint32_t)__half_as_ushort(__float2half(v1.z))
             | ((uint32_t)__half_as_ushort(__float2half(v1.w)) << 16);
        h1.x = (uint32_t)__half_as_ushort(__float2half(v2.x))
             | ((uint32_t)__half_as_ushort(__float2half(v2.y)) << 16);
        h1.y = (uint32_t)__half_as_ushort(__float2half(v2.z))
             | ((uint32_t)__half_as_ushort(__float2half(v2.w)) << 16);
        h1.z = (uint32_t)__half_as_ushort(__float2half(v3.x))
             | ((uint32_t)__half_as_ushort(__float2half(v3.y)) << 16);
        h1.w = (uint32_t)__half_as_ushort(__float2half(v3.z))
             | ((uint32_t)__half_as_ushort(__float2half(v3.w)) << 16);
        int mt = m >> 7, r = m & 127;
        int s  = kq >> 1, b2 = kq & 1;   // K-tile, 16-fp16 half within tile
        int swz = (r >> 1) & 3;
        char* tb = (char*)g_Xh + ((size_t)(mt * KTILES + s)) * TILEB + r * 64;
        *(uint4*)(tb + (((2 * b2)     ^ swz) * 16)) = h0;
        *(uint4*)(tb + (((2 * b2 + 1) ^ swz) * 16)) = h1;
        return;
    }

    // ---- W_eff: 8 e-rows x 256 d-cols per block, tiled output ----
    const int bid = blockIdx.x;
    const int d   = (bid % WEFF_DTILES) * 256 + threadIdx.x;
    const int e0  = (bid / WEFF_DTILES) * WEFF_EROWS;
    const int tx  = threadIdx.x;

    float acc[WEFF_EROWS];
    #pragma unroll
    for (int e = 0; e < WEFF_EROWS; e++) acc[e] = 0.f;

    bool is_q = (e0 < DIM_D);
    bool is_v = (e0 >= 2 * DIM_D);
    if (is_q || is_v) {
        __shared__ float sw[NUM_T];
        __shared__ __align__(16) float sB[NUM_T * RANK_R * WEFF_EROWS];  // [i][e]

        if (tx == 0) {
            float mx = -1e30f;
            float lg[NUM_T];
            #pragma unroll
            for (int t = 0; t < NUM_T; t++) { lg[t] = __ldg(logits + t); mx = fmaxf(mx, lg[t]); }
            float e[NUM_T], se = 0.f;
            #pragma unroll
            for (int t = 0; t < NUM_T; t++) { e[t] = expf(lg[t] - mx); se += e[t]; }
            #pragma unroll
            for (int t = 0; t < NUM_T; t++) {
                float coef = (e[t] / se) * __ldg(alpha + t);
                int sa  = is_q ? t : (20 + t);
                int sb2 = is_q ? (10 + t) : (30 + t);
                float ssa = g_part[4 * sa]  + g_part[4 * sa + 1]
                          + g_part[4 * sa + 2] + g_part[4 * sa + 3];
                float ssb = g_part[4 * sb2] + g_part[4 * sb2 + 1]
                          + g_part[4 * sb2 + 2] + g_part[4 * sb2 + 3];
                sw[t] = coef / (sqrtf(ssa) * sqrtf(ssb) + 1e-8f);
            }
        }
        __syncthreads();

        const float* Am = is_q ? Aq : Av;
        const float* Bm = is_q ? Bq : Bv;
        int el0 = is_q ? e0 : (e0 - 2 * DIM_D);
        for (int idx = tx; idx < NUM_T * RANK_R * WEFF_EROWS; idx += 256) {
            int i = idx >> 3, e = idx & 7;
            int t = i >> 4,  r = i & 15;
            sB[idx] = sw[t] * Bm[((size_t)t * DIM_D + el0 + e) * RANK_R + r];
        }
        __syncthreads();

        const float4* sB4 = (const float4*)sB;
        #pragma unroll 32
        for (int i = 0; i < NUM_T * RANK_R; i++) {
            float a = __ldg(Am + (size_t)i * DIM_D + d);
            float4 b0 = sB4[i * 2 + 0];
            float4 b1 = sB4[i * 2 + 1];
            acc[0] += a * b0.x;  acc[1] += a * b0.y;
            acc[2] += a * b0.z;  acc[3] += a * b0.w;
            acc[4] += a * b1.x;  acc[5] += a * b1.y;
            acc[6] += a * b1.z;  acc[7] += a * b1.w;
        }
    }
    // tiled store: nt = e0>>7, K-tile = d>>5, chunk = (d>>3)&3, byte = (d&7)*2
    {
        int nt = e0 >> 7;
        int s  = d >> 5;
        int c  = (d >> 3) & 3;
        int bo = (d & 7) * 2;
        char* tb = (char*)g_Wh + ((size_t)(nt * KTILES + s)) * TILEB;
        #pragma unroll
        for (int e = 0; e < WEFF_EROWS; e++) {
            float val = qkvw[(size_t)(e0 + e) * DIM_D + d] + acc[e];
            int r = (e0 + e) & 127;
            int swz = (r >> 1) & 3;
            *(unsigned short*)(tb + r * 64 + ((c ^ swz) * 16) + bo) =
                __half_as_ushort(__float2half(val));
        }
    }
}

// ---------------------------------------------------------------------------
// Kernel 3: PERSISTENT HMMA GEMM  out = Xh @ Wh^T + bias
//   304 CTAs (2/SM). Each CTA runs one continuous 3-stage bulk pipeline
//   over all its output tiles (global stage counter q; tile = q/12).
//   Epilogues overlap the next tile's loads; pipeline never drains.
// ---------------------------------------------------------------------------
__global__ __launch_bounds__(256, 2)
void k_gemm_mma(const float* __restrict__ bias, float* __restrict__ out) {
    extern __shared__ __align__(1024) char smem[];
    const uint32_t sb = smem_u32(smem);
    const uint32_t mb = sb + SMEM_MB;
    const int tid = threadIdx.x;
    const int lid = tid & 31;
    const int wid = tid >> 5;
    const int wm = wid & 3;          // 4 warps in M, 32 rows each
    const int wn = wid >> 2;         // 2 warps in N, 64 cols each
    const int cta = blockIdx.x;

    if (tid == 0) {
        #pragma unroll
        for (int j = 0; j < NSTAGE; j++) MBAR_INIT(mb + j * 8, 1);
    }
    __syncthreads();

    const int my_tiles = (NTILES - 1 - cta) / NPERS + 1;   // 7 or 8
    const int total_q  = my_tiles * SPT;

    // issue stage q: tile = cta + (q/12)*NPERS, K-tiles 2s,2s+1 (s = q%12)
    auto issue = [&](int q) {
        int t  = cta + (q / SPT) * NPERS;
        int s  = q % SPT;
        int tm = t / NTILE_N;
        int tn = t - tm * NTILE_N;
        uint32_t m = mb + (uint32_t)(q % NSTAGE) * 8;
        uint32_t dst = sb + (uint32_t)(q % NSTAGE) * GSTAGE;
        const char* srcA = (const char*)g_Xh
            + ((size_t)tm * KTILES + (size_t)s * 2) * TILEB;
        const char* srcB = (const char*)g_Wh
            + ((size_t)tn * KTILES + (size_t)s * 2) * TILEB;
        MBAR_EXPECT_TX(m, GSTAGE);
        BULK_G2S(dst,             srcA, 2 * TILEB, m);
        BULK_G2S(dst + 2 * TILEB, srcB, 2 * TILEB, m);
    };

    if (tid == 0) { issue(0); if (total_q > 1) issue(1); }

    float acc[2][8][4];
    #pragma unroll
    for (int i = 0; i < 2; i++)
        #pragma unroll
        for (int j = 0; j < 8; j++)
            #pragma unroll
            for (int q2 = 0; q2 < 4; q2++) acc[i][j][q2] = 0.f;

    // per-lane constants (swizzle matches writer: c' = c ^ ((r>>1)&3))
    const int aRow  = wm * 32 + (lid & 15);
    const int aSwz  = ((lid & 15) >> 1) & 3;
    const int aCh   = lid >> 4;                       // 0/1
    const int bRow  = (lid < 16) ? (lid & 7) : 8 + (lid & 7);
    const int bSwz  = (bRow >> 1) & 3;
    const int bCh   = (lid >> 3) & 1;                 // 0/1

    for (int q = 0; q < total_q; q++) {
        MBAR_WAIT(mb + (uint32_t)(q % NSTAGE) * 8, (q / NSTAGE) & 1);
        __syncthreads();                  // all warps done with stage q-1
        if (tid == 0 && q + 2 < total_q) issue(q + 2);

        uint32_t stage = sb + (uint32_t)(q % NSTAGE) * GSTAGE;
        #pragma unroll
        for (int kt = 0; kt < 2; kt++) {
            uint32_t bufA = stage + (uint32_t)kt * TILEB;
            uint32_t bufB = stage + 2 * TILEB + (uint32_t)kt * TILEB;
            #pragma unroll
            for (int kk = 0; kk < 2; kk++) {
                uint32_t cA = (uint32_t)(((kk * 2 + aCh) ^ aSwz) * 16);
                uint32_t ra[2][4];
                #pragma unroll
                for (int mt = 0; mt < 2; mt++)
                    ldsm_x4(ra[mt], bufA + (uint32_t)(aRow + mt * 16) * 64 + cA);
                uint32_t cB = (uint32_t)(((kk * 2 + bCh) ^ bSwz) * 16);
                #pragma unroll
                for (int half = 0; half < 2; half++) {
                    uint32_t rb[2][4];
                    #pragma unroll
                    for (int g = 0; g < 2; g++)
                        ldsm_x4(rb[g], bufB +
                            (uint32_t)(wn * 64 + (half * 2 + g) * 16 + bRow) * 64 + cB);
                    #pragma unroll
                    for (int mt = 0; mt < 2; mt++)
                        #pragma unroll
                        for (int n4 = 0; n4 < 4; n4++) {
                            uint32_t b0 = rb[n4 >> 1][(n4 & 1) * 2];
                            uint32_t b1 = rb[n4 >> 1][(n4 & 1) * 2 + 1];
                            mma_fp16(acc[mt][half * 4 + n4], ra[mt], b0, b1);
                        }
                }
            }
        }

        if ((q % SPT) == SPT - 1) {
            // Epilogue for finished tile (overlaps next tile's bulk loads)
            int t  = cta + (q / SPT) * NPERS;
            int tm = t / NTILE_N;
            int tn = t - tm * NTILE_N;
            const int r0 = tm * BM + wm * 32 + (lid >> 2);
            const int cb = tn * BN + wn * 64 + (lid & 3) * 2;
            #pragma unroll
            for (int nt = 0; nt < 8; nt++) {
                float2 bv = *(const float2*)(bias + cb + nt * 8);
                #pragma unroll
                for (int mt = 0; mt < 2; mt++) {
                    int r = r0 + mt * 16;
                    float2 v0 = make_float2(acc[mt][nt][0] + bv.x, acc[mt][nt][1] + bv.y);
                    float2 v1 = make_float2(acc[mt][nt][2] + bv.x, acc[mt][nt][3] + bv.y);
                    *(float2*)(out + (size_t)r * DIM_N + cb + nt * 8) = v0;
                    *(float2*)(out + (size_t)(r + 8) * DIM_N + cb + nt * 8) = v1;
                    acc[mt][nt][0] = 0.f; acc[mt][nt][1] = 0.f;
                    acc[mt][nt][2] = 0.f; acc[mt][nt][3] = 0.f;
                }
            }
        }
    }
}

// ---------------------------------------------------------------------------
// Launch
// ---------------------------------------------------------------------------
extern "C" void kernel_launch(void* const* d_in, const int* in_sizes, int n_in,
                              void* d_out, int out_size) {
    const float* x      = (const float*)d_in[0];
    const float* Aq     = (const float*)d_in[1];
    const float* Bq     = (const float*)d_in[2];
    const float* Av     = (const float*)d_in[3];
    const float* Bv     = (const float*)d_in[4];
    const float* qkvw   = (const float*)d_in[5];
    const float* qkvb   = (const float*)d_in[6];
    const float* logits = (const float*)d_in[7];
    const float* alpha  = (const float*)d_in[8];
    float* out = (float*)d_out;

    cudaFuncSetAttribute(k_gemm_mma, cudaFuncAttributeMaxDynamicSharedMemorySize, SMEM_TOTAL);

    k_sumsq   <<<NSUMSQ_BLOCKS, 256>>>(Aq, Bq, Av, Bv);
    k_prep1   <<<NWEFF_BLOCKS + NCONV_BLOCKS, 256>>>(
                  x, Aq, Bq, Av, Bv, qkvw, logits, alpha);
    k_gemm_mma<<<NPERS, 256, SMEM_TOTAL>>>(qkvb, out);
}